// round 2
// baseline (speedup 1.0000x reference)
#include <cuda_runtime.h>
#include <cuda_bf16.h>
#include <math.h>

// Problem constants
#define BZ       16
#define SEG_LEN  16
#define NUM_SEGS 256
#define HH       512
#define NHH      8
#define HD       64
#define SS       4097                 // NUM_SEGS*SEG_LEN + 1
#define NSEG     (BZ * NUM_SEGS)     // 4096
#define LL       18                  // SEG_LEN + 2
#define TOK      (NSEG * LL)         // 73728
#define FTOK     (BZ * SS)           // 65552 (FFN tokens)
#define LN_EPS   1e-5f

// ---------------- scratch (__device__ globals; zero-init bss) ----------------
__device__ float g_segs[(size_t)TOK * HH];
__device__ float g_q   [(size_t)TOK * HH];
__device__ float g_k   [(size_t)TOK * HH];
__device__ float g_v   [(size_t)TOK * HH];
__device__ float g_att [(size_t)TOK * HH];
__device__ float g_o   [(size_t)TOK * HH];
__device__ float g_proc[(size_t)FTOK * HH];
__device__ float g_act [(size_t)FTOK * 2 * HH];

// ---------------- build segs: [N_seg, 18, H] with start/end markers ----------
__global__ void build_segs_kernel(const float* __restrict__ hid,
                                  const float* __restrict__ st,
                                  const float* __restrict__ en) {
    // one float4 per thread over TOK*H/4 = 9,437,184 elements
    size_t i4 = (size_t)blockIdx.x * blockDim.x + threadIdx.x;
    int row = (int)(i4 / (HH / 4));
    int c4  = (int)(i4 % (HH / 4));
    int n = row / LL, l = row % LL;
    const float4* src;
    if (l == 0)            src = (const float4*)st;
    else if (l == LL - 1)  src = (const float4*)en;
    else {
        int b = n / NUM_SEGS, seg = n % NUM_SEGS;
        src = (const float4*)(hid + ((size_t)b * SS + (size_t)seg * SEG_LEN + (l - 1)) * HH);
    }
    ((float4*)g_segs)[i4] = src[c4];
}

// ---------------- SGEMM: C[M,N] = A[M,K] @ W[K,N] + bias (+epilogue) --------
// EPI: 0 = +bias ; 1 = gelu(x+bias) ; 2 = x+bias+res[row,col]
__device__ __forceinline__ float gelu_exact(float x) {
    return 0.5f * x * (1.0f + erff(x * 0.70710678118654752f));
}

template <int EPI>
__global__ __launch_bounds__(256)
void sgemm_kernel(const float* __restrict__ A, const float* __restrict__ W,
                  const float* __restrict__ bias, const float* __restrict__ res,
                  float* __restrict__ C, int M, int N, int K) {
    __shared__ float As[8][128];
    __shared__ float Bs[8][128];

    const int tid = threadIdx.x;
    const int tx = tid & 15;          // 0..15 -> N
    const int ty = tid >> 4;          // 0..15 -> M
    const int m0 = blockIdx.y * 128;
    const int n0 = blockIdx.x * 128;

    // A tile loader: 128 rows x 8 k, float4 along K
    const int arow = m0 + (tid >> 1);
    const int ak   = (tid & 1) * 4;
    const bool avalid = (arow < M);
    const float* Aptr = A + (size_t)(avalid ? arow : 0) * K + ak;

    // B tile loader: 8 k-rows x 128 cols, float4 along N
    const int brow = tid >> 5;
    const int bcol = (tid & 31) * 4;
    const float* Wptr = W + (size_t)brow * N + n0 + bcol;

    float acc[8][8];
#pragma unroll
    for (int i = 0; i < 8; i++)
#pragma unroll
        for (int j = 0; j < 8; j++) acc[i][j] = 0.f;

    for (int k0 = 0; k0 < K; k0 += 8) {
        float4 av = avalid ? *(const float4*)Aptr : make_float4(0.f, 0.f, 0.f, 0.f);
        float4 bv = *(const float4*)Wptr;
        Aptr += 8;
        Wptr += (size_t)8 * N;

        __syncthreads();
        As[ak + 0][tid >> 1] = av.x;
        As[ak + 1][tid >> 1] = av.y;
        As[ak + 2][tid >> 1] = av.z;
        As[ak + 3][tid >> 1] = av.w;
        *(float4*)&Bs[brow][bcol] = bv;
        __syncthreads();

#pragma unroll
        for (int kk = 0; kk < 8; kk++) {
            float4 a0 = *(const float4*)&As[kk][ty * 4];
            float4 a1 = *(const float4*)&As[kk][64 + ty * 4];
            float4 b0 = *(const float4*)&Bs[kk][tx * 4];
            float4 b1 = *(const float4*)&Bs[kk][64 + tx * 4];
            float a[8] = {a0.x, a0.y, a0.z, a0.w, a1.x, a1.y, a1.z, a1.w};
            float b[8] = {b0.x, b0.y, b0.z, b0.w, b1.x, b1.y, b1.z, b1.w};
#pragma unroll
            for (int i = 0; i < 8; i++)
#pragma unroll
                for (int j = 0; j < 8; j++) acc[i][j] = fmaf(a[i], b[j], acc[i][j]);
        }
    }

#pragma unroll
    for (int i = 0; i < 8; i++) {
        int row = m0 + ((i < 4) ? (ty * 4 + i) : (64 + ty * 4 + i - 4));
        if (row >= M) continue;
#pragma unroll
        for (int j = 0; j < 8; j++) {
            int col = n0 + ((j < 4) ? (tx * 4 + j) : (64 + tx * 4 + j - 4));
            float vv = acc[i][j] + bias[col];
            if (EPI == 1) vv = gelu_exact(vv);
            if (EPI == 2) vv += res[(size_t)row * N + col];
            C[(size_t)row * N + col] = vv;
        }
    }
}

// ---------------- attention per (segment, head) ------------------------------
__global__ __launch_bounds__(128)
void attn_kernel(const float* __restrict__ q, const float* __restrict__ k,
                 const float* __restrict__ v, float* __restrict__ out) {
    const int n = blockIdx.x >> 3;
    const int h = blockIdx.x & 7;
    __shared__ float qs[LL * HD], ks[LL * HD], vs[LL * HD];
    __shared__ float sc[LL][LL];

    const size_t base = (size_t)n * LL * HH + (size_t)h * HD;
    for (int i = threadIdx.x; i < LL * HD; i += 128) {
        int r = i >> 6, c = i & 63;
        size_t idx = base + (size_t)r * HH + c;
        qs[i] = q[idx];
        ks[i] = k[idx];
        vs[i] = v[idx];
    }
    __syncthreads();

    for (int s = threadIdx.x; s < LL * LL; s += 128) {
        int qi = s / LL, kj = s % LL;
        float d = 0.f;
#pragma unroll
        for (int c = 0; c < HD; c++) d = fmaf(qs[qi * HD + c], ks[kj * HD + c], d);
        sc[qi][kj] = d * 0.125f;  // 1/sqrt(64)
    }
    __syncthreads();

    if (threadIdx.x < LL) {
        int r = threadIdx.x;
        float m = -1e30f;
#pragma unroll
        for (int j = 0; j < LL; j++) m = fmaxf(m, sc[r][j]);
        float sum = 0.f;
#pragma unroll
        for (int j = 0; j < LL; j++) { float e = __expf(sc[r][j] - m); sc[r][j] = e; sum += e; }
        float inv = 1.f / sum;
#pragma unroll
        for (int j = 0; j < LL; j++) sc[r][j] *= inv;
    }
    __syncthreads();

    for (int s = threadIdx.x; s < LL * HD; s += 128) {
        int qi = s >> 6, d = s & 63;
        float a = 0.f;
#pragma unroll
        for (int j = 0; j < LL; j++) a = fmaf(sc[qi][j], vs[j * HD + d], a);
        out[base + (size_t)qi * HH + d] = a;
    }
}

// ---------------- LayerNorm + strip markers + scatter into processed ---------
__global__ __launch_bounds__(256)
void ln_scatter_kernel(const float* __restrict__ o, const float* __restrict__ gg,
                       const float* __restrict__ bb, float* __restrict__ proc) {
    const int row = blockIdx.x;
    const int l = row % LL;
    if (l == 0 || l == LL - 1) return;

    const float* x = o + (size_t)row * HH;
    const int t = threadIdx.x;
    float v0 = x[t], v1 = x[t + 256];
    float s = v0 + v1, ss = v0 * v0 + v1 * v1;
#pragma unroll
    for (int off = 16; off > 0; off >>= 1) {
        s  += __shfl_xor_sync(0xffffffffu, s,  off);
        ss += __shfl_xor_sync(0xffffffffu, ss, off);
    }
    __shared__ float sh_s[8], sh_ss[8];
    __shared__ float sh_mu, sh_inv;
    if ((t & 31) == 0) { sh_s[t >> 5] = s; sh_ss[t >> 5] = ss; }
    __syncthreads();
    if (t == 0) {
        float ts = 0.f, tss = 0.f;
#pragma unroll
        for (int w = 0; w < 8; w++) { ts += sh_s[w]; tss += sh_ss[w]; }
        float mu = ts / (float)HH;
        float var = tss / (float)HH - mu * mu;
        sh_mu = mu;
        sh_inv = rsqrtf(var + LN_EPS);
    }
    __syncthreads();
    float mu = sh_mu, inv = sh_inv;

    int n = row / LL;
    int b = n >> 8, seg = n & 255;
    size_t orow = (size_t)b * SS + (size_t)seg * SEG_LEN + (l - 1);
    float* dst = proc + orow * HH;
    dst[t]       = (v0 - mu) * inv * gg[t]       + bb[t];
    dst[t + 256] = (v1 - mu) * inv * gg[t + 256] + bb[t + 256];
}

// ---------------- copy last (reason tail) token rows -------------------------
__global__ void copy_last_kernel(const float* __restrict__ hid, float* __restrict__ proc) {
    size_t off = ((size_t)blockIdx.x * SS + (SS - 1)) * HH;
    for (int c = threadIdx.x; c < HH; c += blockDim.x) proc[off + c] = hid[off + c];
}

// ---------------- host launcher ----------------------------------------------
extern "C" void kernel_launch(void* const* d_in, const int* in_sizes, int n_in,
                              void* d_out, int out_size) {
    const float* hid  = (const float*)d_in[0];
    // d_in[1] attention_mask, d_in[2] reason_token_mask: structurally fixed, unused
    const float* st   = (const float*)d_in[3];
    const float* en   = (const float*)d_in[4];
    const float* Wq   = (const float*)d_in[5];
    const float* bq   = (const float*)d_in[6];
    const float* Wk   = (const float*)d_in[7];
    const float* bk   = (const float*)d_in[8];
    const float* Wv   = (const float*)d_in[9];
    const float* bv   = (const float*)d_in[10];
    const float* Wo   = (const float*)d_in[11];
    const float* bo   = (const float*)d_in[12];
    const float* lng  = (const float*)d_in[13];
    const float* lnb  = (const float*)d_in[14];
    const float* W1   = (const float*)d_in[15];
    const float* b1   = (const float*)d_in[16];
    const float* W2   = (const float*)d_in[17];
    const float* b2   = (const float*)d_in[18];
    float* out = (float*)d_out;

    float *segs, *q, *k, *v, *att, *o, *proc, *act;
    cudaGetSymbolAddress((void**)&segs, g_segs);
    cudaGetSymbolAddress((void**)&q,    g_q);
    cudaGetSymbolAddress((void**)&k,    g_k);
    cudaGetSymbolAddress((void**)&v,    g_v);
    cudaGetSymbolAddress((void**)&att,  g_att);
    cudaGetSymbolAddress((void**)&o,    g_o);
    cudaGetSymbolAddress((void**)&proc, g_proc);
    cudaGetSymbolAddress((void**)&act,  g_act);

    // 1. gather segments + markers
    build_segs_kernel<<<(TOK * HH / 4) / 256, 256>>>(hid, st, en);

    // 2. Q,K,V projections: [73728,512] @ [512,512]
    dim3 gproj(HH / 128, TOK / 128);  // (4, 576)
    sgemm_kernel<0><<<gproj, 256>>>(segs, Wq, bq, nullptr, q, TOK, HH, HH);
    sgemm_kernel<0><<<gproj, 256>>>(segs, Wk, bk, nullptr, k, TOK, HH, HH);
    sgemm_kernel<0><<<gproj, 256>>>(segs, Wv, bv, nullptr, v, TOK, HH, HH);

    // 3. per-(segment, head) attention
    attn_kernel<<<NSEG * NHH, 128>>>(q, k, v, att);

    // 4. output projection
    sgemm_kernel<0><<<gproj, 256>>>(att, Wo, bo, nullptr, o, TOK, HH, HH);

    // 5. LayerNorm + scatter (strip markers), plus untouched final token rows
    ln_scatter_kernel<<<TOK, 256>>>(o, lng, lnb, proc);
    copy_last_kernel<<<BZ, 128>>>(hid, proc);

    // 6. FFN: gelu(proc @ W1 + b1) @ W2 + b2 + hidden
    dim3 gf1(2 * HH / 128, (FTOK + 127) / 128);  // (8, 513)
    sgemm_kernel<1><<<gf1, 256>>>(proc, W1, b1, nullptr, act, FTOK, 2 * HH, HH);
    dim3 gf2(HH / 128, (FTOK + 127) / 128);      // (4, 513)
    sgemm_kernel<2><<<gf2, 256>>>(act, W2, b2, hid, out, FTOK, HH, 2 * HH);
}

// round 3
// speedup vs baseline: 1.5169x; 1.5169x over previous
#include <cuda_runtime.h>
#include <cuda_bf16.h>
#include <math.h>
#include <stdint.h>

// Problem constants
#define BZ       16
#define SEG_LEN  16
#define NUM_SEGS 256
#define HH       512
#define NHH      8
#define HD       64
#define SS       4097                 // NUM_SEGS*SEG_LEN + 1
#define NSEG     (BZ * NUM_SEGS)     // 4096
#define LL       18                  // SEG_LEN + 2
#define TOK      (NSEG * LL)         // 73728
#define FTOK     (BZ * SS)           // 65552 (FFN tokens)
#define LN_EPS   1e-5f

// ---------------- scratch (__device__ globals; zero-init bss) ----------------
__device__ float g_segs[(size_t)TOK * HH];
__device__ float g_q   [(size_t)TOK * HH];
__device__ float g_k   [(size_t)TOK * HH];
__device__ float g_v   [(size_t)TOK * HH];
__device__ float g_att [(size_t)TOK * HH];
__device__ float g_o   [(size_t)TOK * HH];
__device__ float g_proc[(size_t)FTOK * HH];
__device__ float g_act [(size_t)FTOK * 2 * HH];

// ---------------- build segs: [N_seg, 18, H] with start/end markers ----------
__global__ void build_segs_kernel(const float* __restrict__ hid,
                                  const float* __restrict__ st,
                                  const float* __restrict__ en) {
    size_t i4 = (size_t)blockIdx.x * blockDim.x + threadIdx.x;
    int row = (int)(i4 / (HH / 4));
    int c4  = (int)(i4 % (HH / 4));
    int n = row / LL, l = row % LL;
    const float4* src;
    if (l == 0)            src = (const float4*)st;
    else if (l == LL - 1)  src = (const float4*)en;
    else {
        int b = n / NUM_SEGS, seg = n % NUM_SEGS;
        src = (const float4*)(hid + ((size_t)b * SS + (size_t)seg * SEG_LEN + (l - 1)) * HH);
    }
    ((float4*)g_segs)[i4] = src[c4];
}

// ---------------- TF32 tensor-core GEMM -------------------------------------
// C[M,N] = A[M,K] @ W[K,N] + bias (+epilogue)
// EPI: 0 = +bias ; 1 = gelu(x+bias) ; 2 = x+bias+res[row,col]
__device__ __forceinline__ float gelu_exact(float x) {
    return 0.5f * x * (1.0f + erff(x * 0.70710678118654752f));
}

__device__ __forceinline__ uint32_t f2tf32(float x) {
    uint32_t u;
    asm("cvt.rna.tf32.f32 %0, %1;" : "=r"(u) : "f"(x));
    return u;
}

#define ASTR 20    // As row stride (floats): conflict-free frag reads
#define BSTR 136   // Bs row stride (floats): conflict-free frag reads

template <int EPI>
__global__ __launch_bounds__(128)
void tgemm_kernel(const float* __restrict__ A, const float* __restrict__ W,
                  const float* __restrict__ bias, const float* __restrict__ res,
                  float* __restrict__ C, int M, int N, int K) {
    __shared__ uint32_t As[128 * ASTR];   // [m][k], 128 x 16 (+pad)
    __shared__ uint32_t Bs[16 * BSTR];    // [k][n], 16 x 128 (+pad)

    const int tid  = threadIdx.x;
    const int warp = tid >> 5;
    const int lane = tid & 31;
    const int g    = lane >> 2;   // group id 0..7
    const int tig  = lane & 3;    // thread-in-group 0..3

    const int m0 = blockIdx.y * 128;
    const int n0 = blockIdx.x * 128;
    const int warp_m = (warp & 1) * 64;
    const int warp_n = (warp >> 1) * 64;

    // global A loader: one row per thread, 16 k per iter (4 float4)
    int arow = m0 + tid; if (arow > M - 1) arow = M - 1;
    const float4* Ag = (const float4*)(A + (size_t)arow * K);
    // global B loader: kk = tid>>5 (+4p), 4 cols per thread
    const int bkk = tid >> 5;
    const int bnc = (lane) * 4;

    float acc[4][8][4];
#pragma unroll
    for (int i = 0; i < 4; i++)
#pragma unroll
        for (int j = 0; j < 8; j++)
#pragma unroll
            for (int c = 0; c < 4; c++) acc[i][j][c] = 0.f;

    float4 pa[4], pb[4];

    auto load_tiles = [&](int k0) {
#pragma unroll
        for (int p = 0; p < 4; p++) pa[p] = Ag[(k0 >> 2) + p];
#pragma unroll
        for (int p = 0; p < 4; p++) {
            int krow = p * 4 + bkk;
            pb[p] = *(const float4*)(W + (size_t)(k0 + krow) * N + n0 + bnc);
        }
    };
    auto store_tiles = [&]() {
#pragma unroll
        for (int p = 0; p < 4; p++) {
            uint32_t* d = &As[tid * ASTR + p * 4];
            d[0] = f2tf32(pa[p].x); d[1] = f2tf32(pa[p].y);
            d[2] = f2tf32(pa[p].z); d[3] = f2tf32(pa[p].w);
        }
#pragma unroll
        for (int p = 0; p < 4; p++) {
            int krow = p * 4 + bkk;
            uint32_t* d = &Bs[krow * BSTR + bnc];
            d[0] = f2tf32(pb[p].x); d[1] = f2tf32(pb[p].y);
            d[2] = f2tf32(pb[p].z); d[3] = f2tf32(pb[p].w);
        }
    };

    auto compute = [&]() {
#pragma unroll
        for (int ks = 0; ks < 16; ks += 8) {
            uint32_t af[4][4], bf[8][2];
#pragma unroll
            for (int mt = 0; mt < 4; mt++) {
                int r = warp_m + mt * 16 + g;
                af[mt][0] = As[(r    ) * ASTR + ks + tig];
                af[mt][1] = As[(r + 8) * ASTR + ks + tig];
                af[mt][2] = As[(r    ) * ASTR + ks + tig + 4];
                af[mt][3] = As[(r + 8) * ASTR + ks + tig + 4];
            }
#pragma unroll
            for (int nt = 0; nt < 8; nt++) {
                int cc = warp_n + nt * 8 + g;
                bf[nt][0] = Bs[(ks + tig    ) * BSTR + cc];
                bf[nt][1] = Bs[(ks + tig + 4) * BSTR + cc];
            }
#pragma unroll
            for (int mt = 0; mt < 4; mt++)
#pragma unroll
                for (int nt = 0; nt < 8; nt++) {
                    asm volatile(
                        "mma.sync.aligned.m16n8k8.row.col.f32.tf32.tf32.f32 "
                        "{%0,%1,%2,%3}, {%4,%5,%6,%7}, {%8,%9}, {%0,%1,%2,%3};\n"
                        : "+f"(acc[mt][nt][0]), "+f"(acc[mt][nt][1]),
                          "+f"(acc[mt][nt][2]), "+f"(acc[mt][nt][3])
                        : "r"(af[mt][0]), "r"(af[mt][1]), "r"(af[mt][2]), "r"(af[mt][3]),
                          "r"(bf[nt][0]), "r"(bf[nt][1]));
                }
        }
    };

    // pipelined mainloop
    load_tiles(0);
    store_tiles();
    __syncthreads();
    for (int k0 = 16; k0 < K; k0 += 16) {
        load_tiles(k0);
        compute();
        __syncthreads();
        store_tiles();
        __syncthreads();
    }
    compute();

    // epilogue
#pragma unroll
    for (int nt = 0; nt < 8; nt++) {
        int col = n0 + warp_n + nt * 8 + 2 * tig;
        float bx = bias[col], by = bias[col + 1];
#pragma unroll
        for (int mt = 0; mt < 4; mt++) {
            int r0 = m0 + warp_m + mt * 16 + g;
            int r1 = r0 + 8;
            float v0 = acc[mt][nt][0] + bx, v1 = acc[mt][nt][1] + by;
            float v2 = acc[mt][nt][2] + bx, v3 = acc[mt][nt][3] + by;
            if (EPI == 1) {
                v0 = gelu_exact(v0); v1 = gelu_exact(v1);
                v2 = gelu_exact(v2); v3 = gelu_exact(v3);
            }
            if (r0 < M) {
                if (EPI == 2) {
                    const float2 rr = *(const float2*)(res + (size_t)r0 * N + col);
                    v0 += rr.x; v1 += rr.y;
                }
                *(float2*)(C + (size_t)r0 * N + col) = make_float2(v0, v1);
            }
            if (r1 < M) {
                if (EPI == 2) {
                    const float2 rr = *(const float2*)(res + (size_t)r1 * N + col);
                    v2 += rr.x; v3 += rr.y;
                }
                *(float2*)(C + (size_t)r1 * N + col) = make_float2(v2, v3);
            }
        }
    }
}

// ---------------- attention per (segment, head) ------------------------------
__global__ __launch_bounds__(128)
void attn_kernel(const float* __restrict__ q, const float* __restrict__ k,
                 const float* __restrict__ v, float* __restrict__ out) {
    const int n = blockIdx.x >> 3;
    const int h = blockIdx.x & 7;
    __shared__ float qs[LL * HD], ks[LL * HD], vs[LL * HD];
    __shared__ float sc[LL][LL];

    const size_t base = (size_t)n * LL * HH + (size_t)h * HD;
    for (int i = threadIdx.x; i < LL * HD; i += 128) {
        int r = i >> 6, c = i & 63;
        size_t idx = base + (size_t)r * HH + c;
        qs[i] = q[idx];
        ks[i] = k[idx];
        vs[i] = v[idx];
    }
    __syncthreads();

    for (int s = threadIdx.x; s < LL * LL; s += 128) {
        int qi = s / LL, kj = s % LL;
        float d = 0.f;
#pragma unroll
        for (int c = 0; c < HD; c++) d = fmaf(qs[qi * HD + c], ks[kj * HD + c], d);
        sc[qi][kj] = d * 0.125f;  // 1/sqrt(64)
    }
    __syncthreads();

    if (threadIdx.x < LL) {
        int r = threadIdx.x;
        float m = -1e30f;
#pragma unroll
        for (int j = 0; j < LL; j++) m = fmaxf(m, sc[r][j]);
        float sum = 0.f;
#pragma unroll
        for (int j = 0; j < LL; j++) { float e = __expf(sc[r][j] - m); sc[r][j] = e; sum += e; }
        float inv = 1.f / sum;
#pragma unroll
        for (int j = 0; j < LL; j++) sc[r][j] *= inv;
    }
    __syncthreads();

    for (int s = threadIdx.x; s < LL * HD; s += 128) {
        int qi = s >> 6, d = s & 63;
        float a = 0.f;
#pragma unroll
        for (int j = 0; j < LL; j++) a = fmaf(sc[qi][j], vs[j * HD + d], a);
        out[base + (size_t)qi * HH + d] = a;
    }
}

// ---------------- LayerNorm + strip markers + scatter into processed ---------
__global__ __launch_bounds__(256)
void ln_scatter_kernel(const float* __restrict__ o, const float* __restrict__ gg,
                       const float* __restrict__ bb, float* __restrict__ proc) {
    const int row = blockIdx.x;
    const int l = row % LL;
    if (l == 0 || l == LL - 1) return;

    const float* x = o + (size_t)row * HH;
    const int t = threadIdx.x;
    float v0 = x[t], v1 = x[t + 256];
    float s = v0 + v1, ss = v0 * v0 + v1 * v1;
#pragma unroll
    for (int off = 16; off > 0; off >>= 1) {
        s  += __shfl_xor_sync(0xffffffffu, s,  off);
        ss += __shfl_xor_sync(0xffffffffu, ss, off);
    }
    __shared__ float sh_s[8], sh_ss[8];
    __shared__ float sh_mu, sh_inv;
    if ((t & 31) == 0) { sh_s[t >> 5] = s; sh_ss[t >> 5] = ss; }
    __syncthreads();
    if (t == 0) {
        float ts = 0.f, tss = 0.f;
#pragma unroll
        for (int w = 0; w < 8; w++) { ts += sh_s[w]; tss += sh_ss[w]; }
        float mu = ts / (float)HH;
        float var = tss / (float)HH - mu * mu;
        sh_mu = mu;
        sh_inv = rsqrtf(var + LN_EPS);
    }
    __syncthreads();
    float mu = sh_mu, inv = sh_inv;

    int n = row / LL;
    int b = n >> 8, seg = n & 255;
    size_t orow = (size_t)b * SS + (size_t)seg * SEG_LEN + (l - 1);
    float* dst = proc + orow * HH;
    dst[t]       = (v0 - mu) * inv * gg[t]       + bb[t];
    dst[t + 256] = (v1 - mu) * inv * gg[t + 256] + bb[t + 256];
}

// ---------------- copy last (reason tail) token rows -------------------------
__global__ void copy_last_kernel(const float* __restrict__ hid, float* __restrict__ proc) {
    size_t off = ((size_t)blockIdx.x * SS + (SS - 1)) * HH;
    for (int c = threadIdx.x; c < HH; c += blockDim.x) proc[off + c] = hid[off + c];
}

// ---------------- host launcher ----------------------------------------------
extern "C" void kernel_launch(void* const* d_in, const int* in_sizes, int n_in,
                              void* d_out, int out_size) {
    const float* hid  = (const float*)d_in[0];
    const float* st   = (const float*)d_in[3];
    const float* en   = (const float*)d_in[4];
    const float* Wq   = (const float*)d_in[5];
    const float* bq   = (const float*)d_in[6];
    const float* Wk   = (const float*)d_in[7];
    const float* bk   = (const float*)d_in[8];
    const float* Wv   = (const float*)d_in[9];
    const float* bv   = (const float*)d_in[10];
    const float* Wo   = (const float*)d_in[11];
    const float* bo   = (const float*)d_in[12];
    const float* lng  = (const float*)d_in[13];
    const float* lnb  = (const float*)d_in[14];
    const float* W1   = (const float*)d_in[15];
    const float* b1   = (const float*)d_in[16];
    const float* W2   = (const float*)d_in[17];
    const float* b2   = (const float*)d_in[18];
    float* out = (float*)d_out;

    float *segs, *q, *k, *v, *att, *o, *proc, *act;
    cudaGetSymbolAddress((void**)&segs, g_segs);
    cudaGetSymbolAddress((void**)&q,    g_q);
    cudaGetSymbolAddress((void**)&k,    g_k);
    cudaGetSymbolAddress((void**)&v,    g_v);
    cudaGetSymbolAddress((void**)&att,  g_att);
    cudaGetSymbolAddress((void**)&o,    g_o);
    cudaGetSymbolAddress((void**)&proc, g_proc);
    cudaGetSymbolAddress((void**)&act,  g_act);

    // 1. gather segments + markers
    build_segs_kernel<<<(TOK * HH / 4) / 256, 256>>>(hid, st, en);

    // 2. Q,K,V projections: [73728,512] @ [512,512]
    dim3 gproj(HH / 128, TOK / 128);  // (4, 576)
    tgemm_kernel<0><<<gproj, 128>>>(segs, Wq, bq, nullptr, q, TOK, HH, HH);
    tgemm_kernel<0><<<gproj, 128>>>(segs, Wk, bk, nullptr, k, TOK, HH, HH);
    tgemm_kernel<0><<<gproj, 128>>>(segs, Wv, bv, nullptr, v, TOK, HH, HH);

    // 3. per-(segment, head) attention
    attn_kernel<<<NSEG * NHH, 128>>>(q, k, v, att);

    // 4. output projection
    tgemm_kernel<0><<<gproj, 128>>>(att, Wo, bo, nullptr, o, TOK, HH, HH);

    // 5. LayerNorm + scatter (strip markers), plus untouched final token rows
    ln_scatter_kernel<<<TOK, 256>>>(o, lng, lnb, proc);
    copy_last_kernel<<<BZ, 128>>>(hid, proc);

    // 6. FFN: gelu(proc @ W1 + b1) @ W2 + b2 + hidden
    dim3 gf1(2 * HH / 128, (FTOK + 127) / 128);  // (8, 513)
    tgemm_kernel<1><<<gf1, 128>>>(proc, W1, b1, nullptr, act, FTOK, 2 * HH, HH);
    dim3 gf2(HH / 128, (FTOK + 127) / 128);      // (4, 513)
    tgemm_kernel<2><<<gf2, 128>>>(act, W2, b2, hid, out, FTOK, HH, 2 * HH);
}

// round 4
// speedup vs baseline: 2.2242x; 1.4663x over previous
#include <cuda_runtime.h>
#include <cuda_bf16.h>
#include <math.h>
#include <stdint.h>

// Problem constants
#define BZ       16
#define SEG_LEN  16
#define NUM_SEGS 256
#define HH       512
#define NHH      8
#define HD       64
#define SS       4097                 // NUM_SEGS*SEG_LEN + 1
#define NSEG     (BZ * NUM_SEGS)     // 4096
#define LL       18                  // SEG_LEN + 2
#define TOK      (NSEG * LL)         // 73728
#define FTOK     (BZ * SS)           // 65552 (FFN tokens)
#define LN_EPS   1e-5f

// ---------------- scratch (__device__ globals; zero-init bss) ----------------
__device__ float g_segs[(size_t)TOK * HH];
__device__ float g_q   [(size_t)TOK * HH];
__device__ float g_k   [(size_t)TOK * HH];
__device__ float g_v   [(size_t)TOK * HH];
__device__ float g_att [(size_t)TOK * HH];
__device__ float g_o   [(size_t)TOK * HH];
__device__ float g_proc[(size_t)FTOK * HH];
__device__ float g_act [(size_t)FTOK * 2 * HH];

// ---------------- build segs: [N_seg, 18, H] with start/end markers ----------
__global__ void build_segs_kernel(const float* __restrict__ hid,
                                  const float* __restrict__ st,
                                  const float* __restrict__ en) {
    size_t i4 = (size_t)blockIdx.x * blockDim.x + threadIdx.x;
    int row = (int)(i4 / (HH / 4));
    int c4  = (int)(i4 % (HH / 4));
    int n = row / LL, l = row % LL;
    const float4* src;
    if (l == 0)            src = (const float4*)st;
    else if (l == LL - 1)  src = (const float4*)en;
    else {
        int b = n / NUM_SEGS, seg = n % NUM_SEGS;
        src = (const float4*)(hid + ((size_t)b * SS + (size_t)seg * SEG_LEN + (l - 1)) * HH);
    }
    ((float4*)g_segs)[i4] = src[c4];
}

// ---------------- TF32 tensor-core GEMM (cp.async double-buffered) ----------
// C[M,N] = A[M,K] @ W[K,N] + bias (+epilogue)
// EPI: 0 = +bias ; 1 = gelu(x+bias) ; 2 = x+bias+res[row,col]
__device__ __forceinline__ float gelu_exact(float x) {
    return 0.5f * x * (1.0f + erff(x * 0.70710678118654752f));
}

__device__ __forceinline__ void cpa16(float* smem_dst, const float* gsrc) {
    uint32_t s = (uint32_t)__cvta_generic_to_shared(smem_dst);
    asm volatile("cp.async.cg.shared.global [%0], [%1], 16;\n" :: "r"(s), "l"(gsrc));
}

#define ASTR 20    // As row stride (floats): conflict-free frag reads, 80B (16B-aligned)
#define BSTR 136   // Bs row stride (floats): conflict-free frag reads, 544B (16B-aligned)

template <int EPI>
__global__ __launch_bounds__(256, 2)
void tgemm_kernel(const float* __restrict__ A, const float* __restrict__ W,
                  const float* __restrict__ bias, const float* __restrict__ res,
                  float* __restrict__ C, int M, int N, int K) {
    __shared__ float As[2][128 * ASTR];   // [m][k], 128 x 16 (+pad)
    __shared__ float Bs[2][16 * BSTR];    // [k][n], 16 x 128 (+pad)

    const int tid  = threadIdx.x;
    const int warp = tid >> 5;
    const int lane = tid & 31;
    const int g    = lane >> 2;   // group 0..7 (row within mma tile)
    const int tig  = lane & 3;    // thread-in-group 0..3 (k / col pair)

    const int m0 = blockIdx.y * 128;
    const int n0 = blockIdx.x * 128;
    const int warp_m = (warp & 1) * 64;        // 2 warps in M
    const int warp_n = (warp >> 1) * 32;       // 4 warps in N

    // A loader: row = tid>>1 (0..127), 2 float4 per thread along k
    int arow = m0 + (tid >> 1); if (arow > M - 1) arow = M - 1;
    const float* Ag = A + (size_t)arow * K + (tid & 1) * 8;
    float* Asd = &As[0][(tid >> 1) * ASTR + (tid & 1) * 8];
    // B loader: krow = tid>>4 (0..15), 2 float4 per thread along n
    const int bkrow = tid >> 4;
    const int bc    = (tid & 15) * 8;
    const float* Bg = W + (size_t)bkrow * N + n0 + bc;
    float* Bsd = &Bs[0][bkrow * BSTR + bc];

    const int nk = K >> 4;

    auto issue = [&](int kt, int buf) {
        const float* ag = Ag + kt * 16;
        float* ad = Asd + buf * 128 * ASTR;
        cpa16(ad, ag); cpa16(ad + 4, ag + 4);
        const float* bg = Bg + (size_t)kt * 16 * N;
        float* bd = Bsd + buf * 16 * BSTR;
        cpa16(bd, bg); cpa16(bd + 4, bg + 4);
        asm volatile("cp.async.commit_group;\n");
    };

    float acc[4][4][4];
#pragma unroll
    for (int i = 0; i < 4; i++)
#pragma unroll
        for (int j = 0; j < 4; j++)
#pragma unroll
            for (int c = 0; c < 4; c++) acc[i][j][c] = 0.f;

    auto compute = [&](int buf) {
        const uint32_t* as = (const uint32_t*)&As[buf][0];
        const uint32_t* bs = (const uint32_t*)&Bs[buf][0];
#pragma unroll
        for (int ks = 0; ks < 16; ks += 8) {
            uint32_t af[4][4], bf[4][2];
#pragma unroll
            for (int mt = 0; mt < 4; mt++) {
                int r = warp_m + mt * 16 + g;
                af[mt][0] = as[(r    ) * ASTR + ks + tig];
                af[mt][1] = as[(r + 8) * ASTR + ks + tig];
                af[mt][2] = as[(r    ) * ASTR + ks + tig + 4];
                af[mt][3] = as[(r + 8) * ASTR + ks + tig + 4];
            }
#pragma unroll
            for (int nt = 0; nt < 4; nt++) {
                int cc = warp_n + nt * 8 + g;
                bf[nt][0] = bs[(ks + tig    ) * BSTR + cc];
                bf[nt][1] = bs[(ks + tig + 4) * BSTR + cc];
            }
#pragma unroll
            for (int mt = 0; mt < 4; mt++)
#pragma unroll
                for (int nt = 0; nt < 4; nt++) {
                    asm volatile(
                        "mma.sync.aligned.m16n8k8.row.col.f32.tf32.tf32.f32 "
                        "{%0,%1,%2,%3}, {%4,%5,%6,%7}, {%8,%9}, {%0,%1,%2,%3};\n"
                        : "+f"(acc[mt][nt][0]), "+f"(acc[mt][nt][1]),
                          "+f"(acc[mt][nt][2]), "+f"(acc[mt][nt][3])
                        : "r"(af[mt][0]), "r"(af[mt][1]), "r"(af[mt][2]), "r"(af[mt][3]),
                          "r"(bf[nt][0]), "r"(bf[nt][1]));
                }
        }
    };

    // pipelined mainloop (2-stage cp.async)
    issue(0, 0);
    issue(1, 1);
    asm volatile("cp.async.wait_group 1;\n");
    __syncthreads();
    for (int kt = 0; kt < nk; kt++) {
        compute(kt & 1);
        __syncthreads();
        if (kt + 2 < nk) {
            issue(kt + 2, kt & 1);
            asm volatile("cp.async.wait_group 1;\n");
        } else {
            asm volatile("cp.async.wait_group 0;\n");
        }
        __syncthreads();
    }

    // epilogue
#pragma unroll
    for (int nt = 0; nt < 4; nt++) {
        int col = n0 + warp_n + nt * 8 + 2 * tig;
        float bx = bias[col], by = bias[col + 1];
#pragma unroll
        for (int mt = 0; mt < 4; mt++) {
            int r0 = m0 + warp_m + mt * 16 + g;
            int r1 = r0 + 8;
            float v0 = acc[mt][nt][0] + bx, v1 = acc[mt][nt][1] + by;
            float v2 = acc[mt][nt][2] + bx, v3 = acc[mt][nt][3] + by;
            if (EPI == 1) {
                v0 = gelu_exact(v0); v1 = gelu_exact(v1);
                v2 = gelu_exact(v2); v3 = gelu_exact(v3);
            }
            if (r0 < M) {
                if (EPI == 2) {
                    const float2 rr = *(const float2*)(res + (size_t)r0 * N + col);
                    v0 += rr.x; v1 += rr.y;
                }
                *(float2*)(C + (size_t)r0 * N + col) = make_float2(v0, v1);
            }
            if (r1 < M) {
                if (EPI == 2) {
                    const float2 rr = *(const float2*)(res + (size_t)r1 * N + col);
                    v2 += rr.x; v3 += rr.y;
                }
                *(float2*)(C + (size_t)r1 * N + col) = make_float2(v2, v3);
            }
        }
    }
}

// ---------------- attention per (segment, head) ------------------------------
__global__ __launch_bounds__(128)
void attn_kernel(const float* __restrict__ q, const float* __restrict__ k,
                 const float* __restrict__ v, float* __restrict__ out) {
    const int n = blockIdx.x >> 3;
    const int h = blockIdx.x & 7;
    __shared__ float qs[LL * HD], ks[LL * HD], vs[LL * HD];
    __shared__ float sc[LL][LL];

    const size_t base = (size_t)n * LL * HH + (size_t)h * HD;
    for (int i = threadIdx.x; i < LL * HD; i += 128) {
        int r = i >> 6, c = i & 63;
        size_t idx = base + (size_t)r * HH + c;
        qs[i] = q[idx];
        ks[i] = k[idx];
        vs[i] = v[idx];
    }
    __syncthreads();

    for (int s = threadIdx.x; s < LL * LL; s += 128) {
        int qi = s / LL, kj = s % LL;
        float d = 0.f;
#pragma unroll
        for (int c = 0; c < HD; c++) d = fmaf(qs[qi * HD + c], ks[kj * HD + c], d);
        sc[qi][kj] = d * 0.125f;  // 1/sqrt(64)
    }
    __syncthreads();

    if (threadIdx.x < LL) {
        int r = threadIdx.x;
        float m = -1e30f;
#pragma unroll
        for (int j = 0; j < LL; j++) m = fmaxf(m, sc[r][j]);
        float sum = 0.f;
#pragma unroll
        for (int j = 0; j < LL; j++) { float e = __expf(sc[r][j] - m); sc[r][j] = e; sum += e; }
        float inv = 1.f / sum;
#pragma unroll
        for (int j = 0; j < LL; j++) sc[r][j] *= inv;
    }
    __syncthreads();

    for (int s = threadIdx.x; s < LL * HD; s += 128) {
        int qi = s >> 6, d = s & 63;
        float a = 0.f;
#pragma unroll
        for (int j = 0; j < LL; j++) a = fmaf(sc[qi][j], vs[j * HD + d], a);
        out[base + (size_t)qi * HH + d] = a;
    }
}

// ---------------- LayerNorm + strip markers + scatter into processed ---------
__global__ __launch_bounds__(256)
void ln_scatter_kernel(const float* __restrict__ o, const float* __restrict__ gg,
                       const float* __restrict__ bb, float* __restrict__ proc) {
    const int row = blockIdx.x;
    const int l = row % LL;
    if (l == 0 || l == LL - 1) return;

    const float* x = o + (size_t)row * HH;
    const int t = threadIdx.x;
    float v0 = x[t], v1 = x[t + 256];
    float s = v0 + v1, ss = v0 * v0 + v1 * v1;
#pragma unroll
    for (int off = 16; off > 0; off >>= 1) {
        s  += __shfl_xor_sync(0xffffffffu, s,  off);
        ss += __shfl_xor_sync(0xffffffffu, ss, off);
    }
    __shared__ float sh_s[8], sh_ss[8];
    __shared__ float sh_mu, sh_inv;
    if ((t & 31) == 0) { sh_s[t >> 5] = s; sh_ss[t >> 5] = ss; }
    __syncthreads();
    if (t == 0) {
        float ts = 0.f, tss = 0.f;
#pragma unroll
        for (int w = 0; w < 8; w++) { ts += sh_s[w]; tss += sh_ss[w]; }
        float mu = ts / (float)HH;
        float var = tss / (float)HH - mu * mu;
        sh_mu = mu;
        sh_inv = rsqrtf(var + LN_EPS);
    }
    __syncthreads();
    float mu = sh_mu, inv = sh_inv;

    int n = row / LL;
    int b = n >> 8, seg = n & 255;
    size_t orow = (size_t)b * SS + (size_t)seg * SEG_LEN + (l - 1);
    float* dst = proc + orow * HH;
    dst[t]       = (v0 - mu) * inv * gg[t]       + bb[t];
    dst[t + 256] = (v1 - mu) * inv * gg[t + 256] + bb[t + 256];
}

// ---------------- copy last (reason tail) token rows -------------------------
__global__ void copy_last_kernel(const float* __restrict__ hid, float* __restrict__ proc) {
    size_t off = ((size_t)blockIdx.x * SS + (SS - 1)) * HH;
    for (int c = threadIdx.x; c < HH; c += blockDim.x) proc[off + c] = hid[off + c];
}

// ---------------- host launcher ----------------------------------------------
extern "C" void kernel_launch(void* const* d_in, const int* in_sizes, int n_in,
                              void* d_out, int out_size) {
    const float* hid  = (const float*)d_in[0];
    const float* st   = (const float*)d_in[3];
    const float* en   = (const float*)d_in[4];
    const float* Wq   = (const float*)d_in[5];
    const float* bq   = (const float*)d_in[6];
    const float* Wk   = (const float*)d_in[7];
    const float* bk   = (const float*)d_in[8];
    const float* Wv   = (const float*)d_in[9];
    const float* bv   = (const float*)d_in[10];
    const float* Wo   = (const float*)d_in[11];
    const float* bo   = (const float*)d_in[12];
    const float* lng  = (const float*)d_in[13];
    const float* lnb  = (const float*)d_in[14];
    const float* W1   = (const float*)d_in[15];
    const float* b1   = (const float*)d_in[16];
    const float* W2   = (const float*)d_in[17];
    const float* b2   = (const float*)d_in[18];
    float* out = (float*)d_out;

    float *segs, *q, *k, *v, *att, *o, *proc, *act;
    cudaGetSymbolAddress((void**)&segs, g_segs);
    cudaGetSymbolAddress((void**)&q,    g_q);
    cudaGetSymbolAddress((void**)&k,    g_k);
    cudaGetSymbolAddress((void**)&v,    g_v);
    cudaGetSymbolAddress((void**)&att,  g_att);
    cudaGetSymbolAddress((void**)&o,    g_o);
    cudaGetSymbolAddress((void**)&proc, g_proc);
    cudaGetSymbolAddress((void**)&act,  g_act);

    // 1. gather segments + markers
    build_segs_kernel<<<(TOK * HH / 4) / 256, 256>>>(hid, st, en);

    // 2. Q,K,V projections: [73728,512] @ [512,512]
    dim3 gproj(HH / 128, TOK / 128);  // (4, 576)
    tgemm_kernel<0><<<gproj, 256>>>(segs, Wq, bq, nullptr, q, TOK, HH, HH);
    tgemm_kernel<0><<<gproj, 256>>>(segs, Wk, bk, nullptr, k, TOK, HH, HH);
    tgemm_kernel<0><<<gproj, 256>>>(segs, Wv, bv, nullptr, v, TOK, HH, HH);

    // 3. per-(segment, head) attention
    attn_kernel<<<NSEG * NHH, 128>>>(q, k, v, att);

    // 4. output projection
    tgemm_kernel<0><<<gproj, 256>>>(att, Wo, bo, nullptr, o, TOK, HH, HH);

    // 5. LayerNorm + scatter (strip markers), plus untouched final token rows
    ln_scatter_kernel<<<TOK, 256>>>(o, lng, lnb, proc);
    copy_last_kernel<<<BZ, 128>>>(hid, proc);

    // 6. FFN: gelu(proc @ W1 + b1) @ W2 + b2 + hidden
    dim3 gf1(2 * HH / 128, (FTOK + 127) / 128);  // (8, 513)
    tgemm_kernel<1><<<gf1, 256>>>(proc, W1, b1, nullptr, act, FTOK, 2 * HH, HH);
    dim3 gf2(HH / 128, (FTOK + 127) / 128);      // (4, 513)
    tgemm_kernel<2><<<gf2, 256>>>(act, W2, b2, hid, out, FTOK, HH, 2 * HH);
}

// round 5
// speedup vs baseline: 2.2565x; 1.0145x over previous
#include <cuda_runtime.h>
#include <cuda_bf16.h>
#include <math.h>
#include <stdint.h>

// Problem constants
#define BZ       16
#define SEG_LEN  16
#define NUM_SEGS 256
#define HH       512
#define NHH      8
#define HD       64
#define SS       4097                 // NUM_SEGS*SEG_LEN + 1
#define NSEG     (BZ * NUM_SEGS)     // 4096
#define LL       18                  // SEG_LEN + 2
#define TOK      (NSEG * LL)         // 73728
#define FTOK     (BZ * SS)           // 65552 (FFN tokens)
#define LN_EPS   1e-5f

// ---------------- scratch (__device__ globals; zero-init bss) ----------------
__device__ float g_segs[(size_t)TOK * HH];
__device__ float g_q   [(size_t)TOK * HH];
__device__ float g_k   [(size_t)TOK * HH];
__device__ float g_v   [(size_t)TOK * HH];
__device__ float g_att [(size_t)TOK * HH];
__device__ float g_o   [(size_t)TOK * HH];
__device__ float g_proc[(size_t)FTOK * HH];
__device__ float g_act [(size_t)FTOK * 2 * HH];

// ---------------- build segs: [N_seg, 18, H] with start/end markers ----------
__global__ void build_segs_kernel(const float* __restrict__ hid,
                                  const float* __restrict__ st,
                                  const float* __restrict__ en) {
    size_t i4 = (size_t)blockIdx.x * blockDim.x + threadIdx.x;
    int row = (int)(i4 / (HH / 4));
    int c4  = (int)(i4 % (HH / 4));
    int n = row / LL, l = row % LL;
    const float4* src;
    if (l == 0)            src = (const float4*)st;
    else if (l == LL - 1)  src = (const float4*)en;
    else {
        int b = n / NUM_SEGS, seg = n % NUM_SEGS;
        src = (const float4*)(hid + ((size_t)b * SS + (size_t)seg * SEG_LEN + (l - 1)) * HH);
    }
    ((float4*)g_segs)[i4] = src[c4];
}

// ---------------- TF32 tensor-core GEMM (3-stage cp.async, 128x256 block) ----
// C[M,N] = A[M,K] @ W[K,N] + bias (+epilogue)
// EPI: 0 = +bias ; 1 = gelu(x+bias) ; 2 = x+bias+res[row,col]
__device__ __forceinline__ float gelu_exact(float x) {
    return 0.5f * x * (1.0f + erff(x * 0.70710678118654752f));
}

__device__ __forceinline__ void cpa16(float* smem_dst, const float* gsrc) {
    uint32_t s = (uint32_t)__cvta_generic_to_shared(smem_dst);
    asm volatile("cp.async.cg.shared.global [%0], [%1], 16;\n" :: "r"(s), "l"(gsrc));
}

#define ASTR   20                    // As row stride (floats), conflict-free
#define BSTR   264                   // Bs row stride (floats), conflict-free
#define A_STG  (128 * ASTR)          // floats per A stage
#define B_STG  (16 * BSTR)           // floats per B stage
#define NSTAGE 3
#define GEMM_SMEM ((NSTAGE * (A_STG + B_STG)) * 4)   // 81,408 bytes

template <int EPI>
__global__ __launch_bounds__(256, 1)
void tgemm_kernel(const float* __restrict__ A, const float* __restrict__ W,
                  const float* __restrict__ bias, const float* __restrict__ res,
                  float* __restrict__ C, int M, int N, int K) {
    extern __shared__ float sm[];
    float* As = sm;                       // [NSTAGE][128][ASTR]
    float* Bs = sm + NSTAGE * A_STG;      // [NSTAGE][16][BSTR]

    const int tid  = threadIdx.x;
    const int warp = tid >> 5;
    const int lane = tid & 31;
    const int g    = lane >> 2;   // 0..7
    const int tig  = lane & 3;    // 0..3

    const int m0 = blockIdx.y * 128;
    const int n0 = blockIdx.x * 256;
    const int warp_m = (warp & 1) * 64;    // 2 warps in M
    const int warp_n = (warp >> 1) * 64;   // 4 warps in N

    // A loader: row = tid>>1, 8 floats (2 x cpa16) along k
    int arow = m0 + (tid >> 1); if (arow > M - 1) arow = M - 1;
    const float* Ag = A + (size_t)arow * K + (tid & 1) * 8;
    float* Asd = As + (tid >> 1) * ASTR + (tid & 1) * 8;
    // B loader: krow = tid>>4 (0..15), 16 floats (4 x cpa16) along n
    const int bkrow = tid >> 4;
    const int bc    = (tid & 15) * 16;
    const float* Bg = W + (size_t)bkrow * N + n0 + bc;
    float* Bsd = Bs + bkrow * BSTR + bc;

    const int nk = K >> 4;

    auto issue_body = [&](int kt) {
        int buf = kt % NSTAGE;
        const float* ag = Ag + kt * 16;
        float* ad = Asd + buf * A_STG;
        cpa16(ad, ag); cpa16(ad + 4, ag + 4);
        const float* bg = Bg + (size_t)kt * 16 * N;
        float* bd = Bsd + buf * B_STG;
#pragma unroll
        for (int j = 0; j < 4; j++) cpa16(bd + j * 4, bg + j * 4);
    };

    float acc[4][8][4];
#pragma unroll
    for (int i = 0; i < 4; i++)
#pragma unroll
        for (int j = 0; j < 8; j++)
#pragma unroll
            for (int c = 0; c < 4; c++) acc[i][j][c] = 0.f;

    auto compute = [&](int buf) {
        const uint32_t* as = (const uint32_t*)(As + buf * A_STG);
        const uint32_t* bs = (const uint32_t*)(Bs + buf * B_STG);
#pragma unroll
        for (int ks = 0; ks < 16; ks += 8) {
            uint32_t af[4][4], bf[8][2];
#pragma unroll
            for (int mt = 0; mt < 4; mt++) {
                int r = warp_m + mt * 16 + g;
                af[mt][0] = as[(r    ) * ASTR + ks + tig];
                af[mt][1] = as[(r + 8) * ASTR + ks + tig];
                af[mt][2] = as[(r    ) * ASTR + ks + tig + 4];
                af[mt][3] = as[(r + 8) * ASTR + ks + tig + 4];
            }
#pragma unroll
            for (int nt = 0; nt < 8; nt++) {
                int cc = warp_n + nt * 8 + g;
                bf[nt][0] = bs[(ks + tig    ) * BSTR + cc];
                bf[nt][1] = bs[(ks + tig + 4) * BSTR + cc];
            }
#pragma unroll
            for (int mt = 0; mt < 4; mt++)
#pragma unroll
                for (int nt = 0; nt < 8; nt++) {
                    asm volatile(
                        "mma.sync.aligned.m16n8k8.row.col.f32.tf32.tf32.f32 "
                        "{%0,%1,%2,%3}, {%4,%5,%6,%7}, {%8,%9}, {%0,%1,%2,%3};\n"
                        : "+f"(acc[mt][nt][0]), "+f"(acc[mt][nt][1]),
                          "+f"(acc[mt][nt][2]), "+f"(acc[mt][nt][3])
                        : "r"(af[mt][0]), "r"(af[mt][1]), "r"(af[mt][2]), "r"(af[mt][3]),
                          "r"(bf[nt][0]), "r"(bf[nt][1]));
                }
        }
    };

    // prologue: 2 stages in flight
    issue_body(0);
    asm volatile("cp.async.commit_group;\n");
    issue_body(1);
    asm volatile("cp.async.commit_group;\n");

    for (int kt = 0; kt < nk; kt++) {
        asm volatile("cp.async.wait_group 1;\n");
        __syncthreads();
        compute(kt % NSTAGE);
        if (kt + 2 < nk) issue_body(kt + 2);
        asm volatile("cp.async.commit_group;\n");   // may be empty (tail)
    }

    // epilogue
#pragma unroll
    for (int nt = 0; nt < 8; nt++) {
        int col = n0 + warp_n + nt * 8 + 2 * tig;
        float bx = bias[col], by = bias[col + 1];
#pragma unroll
        for (int mt = 0; mt < 4; mt++) {
            int r0 = m0 + warp_m + mt * 16 + g;
            int r1 = r0 + 8;
            float v0 = acc[mt][nt][0] + bx, v1 = acc[mt][nt][1] + by;
            float v2 = acc[mt][nt][2] + bx, v3 = acc[mt][nt][3] + by;
            if (EPI == 1) {
                v0 = gelu_exact(v0); v1 = gelu_exact(v1);
                v2 = gelu_exact(v2); v3 = gelu_exact(v3);
            }
            if (r0 < M) {
                if (EPI == 2) {
                    const float2 rr = *(const float2*)(res + (size_t)r0 * N + col);
                    v0 += rr.x; v1 += rr.y;
                }
                *(float2*)(C + (size_t)r0 * N + col) = make_float2(v0, v1);
            }
            if (r1 < M) {
                if (EPI == 2) {
                    const float2 rr = *(const float2*)(res + (size_t)r1 * N + col);
                    v2 += rr.x; v3 += rr.y;
                }
                *(float2*)(C + (size_t)r1 * N + col) = make_float2(v2, v3);
            }
        }
    }
}

// ---------------- attention per (segment, head) ------------------------------
__global__ __launch_bounds__(128)
void attn_kernel(const float* __restrict__ q, const float* __restrict__ k,
                 const float* __restrict__ v, float* __restrict__ out) {
    const int n = blockIdx.x >> 3;
    const int h = blockIdx.x & 7;
    __shared__ float qs[LL * HD], ks[LL * HD], vs[LL * HD];
    __shared__ float sc[LL][LL];

    const size_t base = (size_t)n * LL * HH + (size_t)h * HD;
    for (int i = threadIdx.x; i < LL * HD; i += 128) {
        int r = i >> 6, c = i & 63;
        size_t idx = base + (size_t)r * HH + c;
        qs[i] = q[idx];
        ks[i] = k[idx];
        vs[i] = v[idx];
    }
    __syncthreads();

    for (int s = threadIdx.x; s < LL * LL; s += 128) {
        int qi = s / LL, kj = s % LL;
        float d = 0.f;
#pragma unroll
        for (int c = 0; c < HD; c++) d = fmaf(qs[qi * HD + c], ks[kj * HD + c], d);
        sc[qi][kj] = d * 0.125f;  // 1/sqrt(64)
    }
    __syncthreads();

    if (threadIdx.x < LL) {
        int r = threadIdx.x;
        float m = -1e30f;
#pragma unroll
        for (int j = 0; j < LL; j++) m = fmaxf(m, sc[r][j]);
        float sum = 0.f;
#pragma unroll
        for (int j = 0; j < LL; j++) { float e = __expf(sc[r][j] - m); sc[r][j] = e; sum += e; }
        float inv = 1.f / sum;
#pragma unroll
        for (int j = 0; j < LL; j++) sc[r][j] *= inv;
    }
    __syncthreads();

    for (int s = threadIdx.x; s < LL * HD; s += 128) {
        int qi = s >> 6, d = s & 63;
        float a = 0.f;
#pragma unroll
        for (int j = 0; j < LL; j++) a = fmaf(sc[qi][j], vs[j * HD + d], a);
        out[base + (size_t)qi * HH + d] = a;
    }
}

// ---------------- LayerNorm + strip markers + scatter into processed ---------
__global__ __launch_bounds__(256)
void ln_scatter_kernel(const float* __restrict__ o, const float* __restrict__ gg,
                       const float* __restrict__ bb, float* __restrict__ proc) {
    const int row = blockIdx.x;
    const int l = row % LL;
    if (l == 0 || l == LL - 1) return;

    const float* x = o + (size_t)row * HH;
    const int t = threadIdx.x;
    float v0 = x[t], v1 = x[t + 256];
    float s = v0 + v1, ss = v0 * v0 + v1 * v1;
#pragma unroll
    for (int off = 16; off > 0; off >>= 1) {
        s  += __shfl_xor_sync(0xffffffffu, s,  off);
        ss += __shfl_xor_sync(0xffffffffu, ss, off);
    }
    __shared__ float sh_s[8], sh_ss[8];
    __shared__ float sh_mu, sh_inv;
    if ((t & 31) == 0) { sh_s[t >> 5] = s; sh_ss[t >> 5] = ss; }
    __syncthreads();
    if (t == 0) {
        float ts = 0.f, tss = 0.f;
#pragma unroll
        for (int w = 0; w < 8; w++) { ts += sh_s[w]; tss += sh_ss[w]; }
        float mu = ts / (float)HH;
        float var = tss / (float)HH - mu * mu;
        sh_mu = mu;
        sh_inv = rsqrtf(var + LN_EPS);
    }
    __syncthreads();
    float mu = sh_mu, inv = sh_inv;

    int n = row / LL;
    int b = n >> 8, seg = n & 255;
    size_t orow = (size_t)b * SS + (size_t)seg * SEG_LEN + (l - 1);
    float* dst = proc + orow * HH;
    dst[t]       = (v0 - mu) * inv * gg[t]       + bb[t];
    dst[t + 256] = (v1 - mu) * inv * gg[t + 256] + bb[t + 256];
}

// ---------------- copy last (reason tail) token rows -------------------------
__global__ void copy_last_kernel(const float* __restrict__ hid, float* __restrict__ proc) {
    size_t off = ((size_t)blockIdx.x * SS + (SS - 1)) * HH;
    for (int c = threadIdx.x; c < HH; c += blockDim.x) proc[off + c] = hid[off + c];
}

// ---------------- host launcher ----------------------------------------------
extern "C" void kernel_launch(void* const* d_in, const int* in_sizes, int n_in,
                              void* d_out, int out_size) {
    const float* hid  = (const float*)d_in[0];
    const float* st   = (const float*)d_in[3];
    const float* en   = (const float*)d_in[4];
    const float* Wq   = (const float*)d_in[5];
    const float* bq   = (const float*)d_in[6];
    const float* Wk   = (const float*)d_in[7];
    const float* bk   = (const float*)d_in[8];
    const float* Wv   = (const float*)d_in[9];
    const float* bv   = (const float*)d_in[10];
    const float* Wo   = (const float*)d_in[11];
    const float* bo   = (const float*)d_in[12];
    const float* lng  = (const float*)d_in[13];
    const float* lnb  = (const float*)d_in[14];
    const float* W1   = (const float*)d_in[15];
    const float* b1   = (const float*)d_in[16];
    const float* W2   = (const float*)d_in[17];
    const float* b2   = (const float*)d_in[18];
    float* out = (float*)d_out;

    float *segs, *q, *k, *v, *att, *o, *proc, *act;
    cudaGetSymbolAddress((void**)&segs, g_segs);
    cudaGetSymbolAddress((void**)&q,    g_q);
    cudaGetSymbolAddress((void**)&k,    g_k);
    cudaGetSymbolAddress((void**)&v,    g_v);
    cudaGetSymbolAddress((void**)&att,  g_att);
    cudaGetSymbolAddress((void**)&o,    g_o);
    cudaGetSymbolAddress((void**)&proc, g_proc);
    cudaGetSymbolAddress((void**)&act,  g_act);

    // allow 81KB dynamic smem for the GEMM kernels (host-side, capture-safe)
    cudaFuncSetAttribute(tgemm_kernel<0>, cudaFuncAttributeMaxDynamicSharedMemorySize, GEMM_SMEM);
    cudaFuncSetAttribute(tgemm_kernel<1>, cudaFuncAttributeMaxDynamicSharedMemorySize, GEMM_SMEM);
    cudaFuncSetAttribute(tgemm_kernel<2>, cudaFuncAttributeMaxDynamicSharedMemorySize, GEMM_SMEM);

    // 1. gather segments + markers
    build_segs_kernel<<<(TOK * HH / 4) / 256, 256>>>(hid, st, en);

    // 2. Q,K,V projections: [73728,512] @ [512,512]
    dim3 gproj(HH / 256, TOK / 128);  // (2, 576)
    tgemm_kernel<0><<<gproj, 256, GEMM_SMEM>>>(segs, Wq, bq, nullptr, q, TOK, HH, HH);
    tgemm_kernel<0><<<gproj, 256, GEMM_SMEM>>>(segs, Wk, bk, nullptr, k, TOK, HH, HH);
    tgemm_kernel<0><<<gproj, 256, GEMM_SMEM>>>(segs, Wv, bv, nullptr, v, TOK, HH, HH);

    // 3. per-(segment, head) attention
    attn_kernel<<<NSEG * NHH, 128>>>(q, k, v, att);

    // 4. output projection
    tgemm_kernel<0><<<gproj, 256, GEMM_SMEM>>>(att, Wo, bo, nullptr, o, TOK, HH, HH);

    // 5. LayerNorm + scatter (strip markers), plus untouched final token rows
    ln_scatter_kernel<<<TOK, 256>>>(o, lng, lnb, proc);
    copy_last_kernel<<<BZ, 128>>>(hid, proc);

    // 6. FFN: gelu(proc @ W1 + b1) @ W2 + b2 + hidden
    dim3 gf1(2 * HH / 256, (FTOK + 127) / 128);  // (4, 513)
    tgemm_kernel<1><<<gf1, 256, GEMM_SMEM>>>(proc, W1, b1, nullptr, act, FTOK, 2 * HH, HH);
    dim3 gf2(HH / 256, (FTOK + 127) / 128);      // (2, 513)
    tgemm_kernel<2><<<gf2, 256, GEMM_SMEM>>>(act, W2, b2, hid, out, FTOK, HH, 2 * HH);
}